// round 1
// baseline (speedup 1.0000x reference)
#include <cuda_runtime.h>

// LoRAConv1D: out = x @ W + b + SCALING * (x @ A) @ B
//   x: [8192, 1600] f32, W: [1600, 4800] f32, b: [4800] f32,
//   A: [1600, 8] f32, B: [8, 4800] f32, out: [8192, 4800] f32
//
// Strategy: fold LoRA into W once per call (W' = W + SCALING*A@B) into a
// __device__ global scratch (alloc-free rule), then run a tiled SGEMM
// out = x @ W' + b.

#define M_TOT 8192
#define N_TOT 4800
#define K_TOT 1600
#define RANK  8
#define LORA_SCALING 4.0f

#define BM 128
#define BN 128
#define BK 16

// 1600 * 4800 * 4B = 30.72 MB scratch for the fused weight.
__device__ float g_Wf[K_TOT * N_TOT];

// ---------------------------------------------------------------------------
// Kernel 1: W' = W + SCALING * (A @ B).  7.68M elements, 8 FMAs each.
// n is the fast dimension -> coalesced B and W accesses; A row broadcast.
// ---------------------------------------------------------------------------
__global__ void fuse_w_kernel(const float* __restrict__ W,
                              const float* __restrict__ A,
                              const float* __restrict__ Bl) {
    int idx = blockIdx.x * blockDim.x + threadIdx.x;
    if (idx >= K_TOT * N_TOT) return;
    int k = idx / N_TOT;
    int n = idx - k * N_TOT;
    float acc = W[idx];
#pragma unroll
    for (int r = 0; r < RANK; r++)
        acc += LORA_SCALING * A[k * RANK + r] * Bl[r * N_TOT + n];
    g_Wf[idx] = acc;
}

// ---------------------------------------------------------------------------
// Kernel 2: SGEMM  out[M,N] = x[M,K] @ W'[K,N] + b[N]
//   128x128 block tile, BK=16, 256 threads, 8x8 per-thread microtile in the
//   strided (4 + 4 at offset 64) layout; double-buffered shared memory.
// M=8192 and K=1600 divide evenly; only the N edge (4800 = 37*128 + 64)
// needs guarding, done at float4 granularity (4800 % 4 == 0).
// ---------------------------------------------------------------------------
__global__ __launch_bounds__(256, 2)
void sgemm_bias_kernel(const float* __restrict__ X,
                       const float* __restrict__ bias,
                       float* __restrict__ out) {
    __shared__ float As[2][BK][BM];   // transposed A tile: As[k][m]
    __shared__ float Bs[2][BK][BN];   // B tile: Bs[k][n]

    const int tid = threadIdx.x;
    const int tx  = tid & 15;         // 0..15 -> column group
    const int ty  = tid >> 4;         // 0..15 -> row group

    const int block_m = blockIdx.y * BM;
    const int block_n = blockIdx.x * BN;

    // ---- load mappings (2 float4 per thread per tile) ----
    // A tile: 128 rows x 16 cols = 512 float4. f -> row = f/4, kq = f%4.
    const int arow = tid >> 2;        // 0..63 (second chunk: +64)
    const int akq  = tid & 3;         // k-quad within the tile
    // B tile: 16 rows x 128 cols = 512 float4. f -> row = f/32, cq = f%32.
    const int brow = tid >> 5;        // 0..7 (second chunk: +8)
    const int bcq  = tid & 31;        // column quad

    const float* Aptr0 = X + (size_t)(block_m + arow)      * K_TOT + akq * 4;
    const float* Aptr1 = X + (size_t)(block_m + arow + 64) * K_TOT + akq * 4;
    const int bcol = block_n + bcq * 4;
    const bool bcol_ok = (bcol < N_TOT);

    float acc[8][8];
#pragma unroll
    for (int i = 0; i < 8; i++)
#pragma unroll
        for (int j = 0; j < 8; j++) acc[i][j] = 0.0f;

    const int nTiles = K_TOT / BK;    // 100

    // ---- preload tile 0 ----
    {
        float4 a0 = *(const float4*)(Aptr0);
        float4 a1 = *(const float4*)(Aptr1);
        float4 b0 = make_float4(0.f, 0.f, 0.f, 0.f);
        float4 b1 = make_float4(0.f, 0.f, 0.f, 0.f);
        if (bcol_ok) {
            b0 = *(const float4*)(g_Wf + (size_t)(brow)     * N_TOT + bcol);
            b1 = *(const float4*)(g_Wf + (size_t)(brow + 8) * N_TOT + bcol);
        }
        As[0][akq * 4 + 0][arow] = a0.x;  As[0][akq * 4 + 1][arow] = a0.y;
        As[0][akq * 4 + 2][arow] = a0.z;  As[0][akq * 4 + 3][arow] = a0.w;
        As[0][akq * 4 + 0][arow + 64] = a1.x;  As[0][akq * 4 + 1][arow + 64] = a1.y;
        As[0][akq * 4 + 2][arow + 64] = a1.z;  As[0][akq * 4 + 3][arow + 64] = a1.w;
        *(float4*)&Bs[0][brow][bcq * 4]     = b0;
        *(float4*)&Bs[0][brow + 8][bcq * 4] = b1;
    }
    __syncthreads();

    int buf = 0;
    for (int t = 0; t < nTiles; t++) {
        // ---- prefetch next tile into registers ----
        float4 pa0, pa1, pb0, pb1;
        if (t + 1 < nTiles) {
            const int k0 = (t + 1) * BK;
            pa0 = *(const float4*)(Aptr0 + k0);
            pa1 = *(const float4*)(Aptr1 + k0);
            pb0 = make_float4(0.f, 0.f, 0.f, 0.f);
            pb1 = make_float4(0.f, 0.f, 0.f, 0.f);
            if (bcol_ok) {
                pb0 = *(const float4*)(g_Wf + (size_t)(k0 + brow)     * N_TOT + bcol);
                pb1 = *(const float4*)(g_Wf + (size_t)(k0 + brow + 8) * N_TOT + bcol);
            }
        }

        // ---- compute on current buffer ----
#pragma unroll
        for (int kk = 0; kk < BK; kk++) {
            float4 a0 = *(const float4*)&As[buf][kk][ty * 4];
            float4 a1 = *(const float4*)&As[buf][kk][64 + ty * 4];
            float4 b0 = *(const float4*)&Bs[buf][kk][tx * 4];
            float4 b1 = *(const float4*)&Bs[buf][kk][64 + tx * 4];
            float ar[8] = {a0.x, a0.y, a0.z, a0.w, a1.x, a1.y, a1.z, a1.w};
            float br[8] = {b0.x, b0.y, b0.z, b0.w, b1.x, b1.y, b1.z, b1.w};
#pragma unroll
            for (int i = 0; i < 8; i++)
#pragma unroll
                for (int j = 0; j < 8; j++)
                    acc[i][j] = fmaf(ar[i], br[j], acc[i][j]);
        }

        // ---- stage prefetched tile into the other buffer ----
        if (t + 1 < nTiles) {
            const int nb = buf ^ 1;
            As[nb][akq * 4 + 0][arow] = pa0.x;  As[nb][akq * 4 + 1][arow] = pa0.y;
            As[nb][akq * 4 + 2][arow] = pa0.z;  As[nb][akq * 4 + 3][arow] = pa0.w;
            As[nb][akq * 4 + 0][arow + 64] = pa1.x;  As[nb][akq * 4 + 1][arow + 64] = pa1.y;
            As[nb][akq * 4 + 2][arow + 64] = pa1.z;  As[nb][akq * 4 + 3][arow + 64] = pa1.w;
            *(float4*)&Bs[nb][brow][bcq * 4]     = pb0;
            *(float4*)&Bs[nb][brow + 8][bcq * 4] = pb1;
        }
        __syncthreads();
        buf ^= 1;
    }

    // ---- epilogue: add bias, store (float4, N-edge guarded per quad) ----
#pragma unroll
    for (int ih = 0; ih < 2; ih++) {
        const int row_base = block_m + ih * 64 + ty * 4;
#pragma unroll
        for (int i = 0; i < 4; i++) {
            const int row = row_base + i;
            const int ai  = ih * 4 + i;
#pragma unroll
            for (int jh = 0; jh < 2; jh++) {
                const int col = block_n + jh * 64 + tx * 4;
                if (col < N_TOT) {
                    const float4 bb = *(const float4*)(bias + col);
                    float4 v;
                    v.x = acc[ai][jh * 4 + 0] + bb.x;
                    v.y = acc[ai][jh * 4 + 1] + bb.y;
                    v.z = acc[ai][jh * 4 + 2] + bb.z;
                    v.w = acc[ai][jh * 4 + 3] + bb.w;
                    *(float4*)(out + (size_t)row * N_TOT + col) = v;
                }
            }
        }
    }
}

// ---------------------------------------------------------------------------
extern "C" void kernel_launch(void* const* d_in, const int* in_sizes, int n_in,
                              void* d_out, int out_size) {
    const float* x  = (const float*)d_in[0];   // [4,2048,1600]
    const float* W  = (const float*)d_in[1];   // [1600,4800]
    const float* b  = (const float*)d_in[2];   // [4800]
    const float* lA = (const float*)d_in[3];   // [1600,8]
    const float* lB = (const float*)d_in[4];   // [8,4800]
    float* out = (float*)d_out;                // [4,2048,4800]

    (void)in_sizes; (void)n_in; (void)out_size;

    // Step 1: fuse LoRA into the weight matrix.
    {
        const int total = K_TOT * N_TOT;
        const int threads = 256;
        const int blocks = (total + threads - 1) / threads;
        fuse_w_kernel<<<blocks, threads>>>(W, lA, lB);
    }

    // Step 2: SGEMM with fused bias.
    {
        dim3 grid((N_TOT + BN - 1) / BN, M_TOT / BM);  // (38, 64)
        sgemm_bias_kernel<<<grid, 256>>>(x, b, out);
    }
}

// round 3
// speedup vs baseline: 2.6259x; 2.6259x over previous
#include <cuda_runtime.h>
#include <cuda_bf16.h>
#include <cstdint>

// LoRAConv1D: out = x @ W + b + 4.0 * (x @ A) @ B
//   x:[8192,1600]f32  W:[1600,4800]f32  b:[4800]  A:[1600,8]  B:[8,4800]
//
// sm_103 (non-'a' PTX target) path: warp-level mma.sync bf16 tensor cores.
//  1) W' = W + 4*A@B, split bf16 hi/lo, stored transposed [N,K]
//  2) x split bf16 hi/lo [M,K]
//  3) GEMM via mma.sync.m16n8k16 bf16, 3 products (xh*Wh + xh*Wl + xl*Wh),
//     fp32 accumulators. BM=128 BN=96 BK=32, 4-stage cp.async pipeline,
//     XOR-swizzled smem + ldmatrix (conflict-free).

#define M_TOT 8192
#define N_TOT 4800
#define K_TOT 1600
#define RANK  8

#define BM 128
#define BN 96
#define BK 32
#define KITERS (K_TOT / BK)        // 50
#define STAGES 4

// stage layout (bytes): Ah[128*64] Al[128*64] Bh[96*64] Bl[96*64]
#define AH_OFF 0
#define AL_OFF 8192
#define BH_OFF 16384
#define BL_OFF 22528
#define STAGE_BYTES 28672
#define SMEM_TOTAL (STAGES * STAGE_BYTES)   // 114688

// ---------------- device scratch (static, alloc-free) ----------------------
__device__ __nv_bfloat16 g_xh[(size_t)M_TOT * K_TOT];
__device__ __nv_bfloat16 g_xl[(size_t)M_TOT * K_TOT];
__device__ __nv_bfloat16 g_wh[(size_t)N_TOT * K_TOT];   // [N,K]
__device__ __nv_bfloat16 g_wl[(size_t)N_TOT * K_TOT];   // [N,K]

// ---------------- helpers ---------------------------------------------------
__device__ __forceinline__ uint32_t smem_u32(const void* p) {
    uint32_t a;
    asm("{ .reg .u64 t; cvta.to.shared.u64 t, %1; cvt.u32.u64 %0, t; }"
        : "=r"(a) : "l"(p));
    return a;
}
// swizzled byte offset within a tile: row pitch 64B, 16B chunks XOR'd so
// both ldmatrix phases (8 rows x 16B) are bank-conflict-free.
__device__ __forceinline__ uint32_t swz(int row, int ch) {
    return (uint32_t)(row * 64 + 16 * (ch ^ (row & 3) ^ ((row >> 2) & 1)));
}
__device__ __forceinline__ void cp16(uint32_t dst, const void* src) {
    asm volatile("cp.async.cg.shared.global [%0], [%1], 16;"
                 :: "r"(dst), "l"(src));
}
#define CP_COMMIT() asm volatile("cp.async.commit_group;")
#define CP_WAIT2()  asm volatile("cp.async.wait_group 2;")

__device__ __forceinline__ void ldm_x4(uint32_t* r, uint32_t addr) {
    asm volatile("ldmatrix.sync.aligned.m8n8.x4.shared.b16 {%0,%1,%2,%3}, [%4];"
                 : "=r"(r[0]), "=r"(r[1]), "=r"(r[2]), "=r"(r[3]) : "r"(addr));
}
__device__ __forceinline__ void ldm_x2(uint32_t* r, uint32_t addr) {
    asm volatile("ldmatrix.sync.aligned.m8n8.x2.shared.b16 {%0,%1}, [%2];"
                 : "=r"(r[0]), "=r"(r[1]) : "r"(addr));
}
__device__ __forceinline__ void mma_bf16(float* d, const uint32_t* a,
                                         const uint32_t* b) {
    asm volatile(
        "mma.sync.aligned.m16n8k16.row.col.f32.bf16.bf16.f32 "
        "{%0,%1,%2,%3}, {%4,%5,%6,%7}, {%8,%9}, {%0,%1,%2,%3};"
        : "+f"(d[0]), "+f"(d[1]), "+f"(d[2]), "+f"(d[3])
        : "r"(a[0]), "r"(a[1]), "r"(a[2]), "r"(a[3]), "r"(b[0]), "r"(b[1]));
}

// ---------------- kernel 1: split x into bf16 hi/lo -------------------------
__global__ void convert_x_kernel(const float* __restrict__ x) {
    size_t base = ((size_t)blockIdx.x * blockDim.x + threadIdx.x) * 8;
    if (base >= (size_t)M_TOT * K_TOT) return;
    float v[8];
    *(float4*)(v)     = *(const float4*)(x + base);
    *(float4*)(v + 4) = *(const float4*)(x + base + 4);
    uint4 ph, pl;
    __nv_bfloat16* hp = (__nv_bfloat16*)&ph;
    __nv_bfloat16* lp = (__nv_bfloat16*)&pl;
#pragma unroll
    for (int j = 0; j < 8; j++) {
        __nv_bfloat16 h = __float2bfloat16(v[j]);
        hp[j] = h;
        lp[j] = __float2bfloat16(v[j] - __bfloat162float(h));
    }
    *(uint4*)((char*)g_xh + base * 2) = ph;
    *(uint4*)((char*)g_xl + base * 2) = pl;
}

// ---------------- kernel 2: W' = W + 4*A@B, split + transpose to [N,K] ------
__global__ void fuse_w_kernel(const float* __restrict__ W,
                              const float* __restrict__ A,
                              const float* __restrict__ Bl) {
    __shared__ __nv_bfloat16 sh[32][33];
    __shared__ __nv_bfloat16 sl[32][33];
    const int n0 = blockIdx.x * 32, k0 = blockIdx.y * 32;
    const int tx = threadIdx.x & 31, ty = threadIdx.x >> 5;   // 32 x 8
#pragma unroll
    for (int rr = 0; rr < 4; rr++) {
        int k = k0 + ty + rr * 8, n = n0 + tx;
        float acc = W[(size_t)k * N_TOT + n];
#pragma unroll
        for (int r = 0; r < RANK; r++)
            acc += 4.0f * A[k * RANK + r] * Bl[r * N_TOT + n];
        __nv_bfloat16 h = __float2bfloat16(acc);
        sh[ty + rr * 8][tx] = h;
        sl[ty + rr * 8][tx] = __float2bfloat16(acc - __bfloat162float(h));
    }
    __syncthreads();
#pragma unroll
    for (int rr = 0; rr < 4; rr++) {
        int n = n0 + ty + rr * 8, k = k0 + tx;
        g_wh[(size_t)n * K_TOT + k] = sh[tx][ty + rr * 8];
        g_wl[(size_t)n * K_TOT + k] = sl[tx][ty + rr * 8];
    }
}

// ---------------- kernel 3: bf16 mma.sync GEMM ------------------------------
__global__ __launch_bounds__(256, 1)
void gemm_kernel(const float* __restrict__ bias, float* __restrict__ out) {
    extern __shared__ char smem[];
    const uint32_t sb = smem_u32(smem);
    const int tid = threadIdx.x, lane = tid & 31, wid = tid >> 5;
    const int wm = wid & 3;          // 0..3 -> 32-row slab
    const int wn = wid >> 2;         // 0..1 -> 48-col slab
    const int m0 = blockIdx.y * BM;
    const int n0 = blockIdx.x * BN;

    // ---- ldmatrix address precompute (kk=0; kk=1 is ^32 on the offset) ----
    uint32_t aOff[2][2];             // [mt][hi/lo]
#pragma unroll
    for (int mt = 0; mt < 2; mt++) {
        int row = wm * 32 + mt * 16 + (lane & 15);
        uint32_t o = swz(row, lane >> 4);
        aOff[mt][0] = AH_OFF + o;
        aOff[mt][1] = AL_OFF + o;
    }
    uint32_t bOff[6][2];             // [nt][hi/lo]
    {
        int l = lane & 15;
#pragma unroll
        for (int nt = 0; nt < 6; nt++) {
            int row = wn * 48 + nt * 8 + (l & 7);
            uint32_t o = swz(row, l >> 3);
            bOff[nt][0] = BH_OFF + o;
            bOff[nt][1] = BL_OFF + o;
        }
    }

    float acc[2][6][4];
#pragma unroll
    for (int i = 0; i < 2; i++)
#pragma unroll
        for (int j = 0; j < 6; j++)
#pragma unroll
            for (int k = 0; k < 4; k++) acc[i][j][k] = 0.0f;

    // ---- stage loader: 1792 x 16B chunks / 256 threads -----------------
    auto load_stage = [&](int s, int k0) {
        const uint32_t st = sb + s * STAGE_BYTES;
#pragma unroll
        for (int i = 0; i < 2; i++) {              // A hi+lo: 512 idx each
            int idx = tid + i * 256;
            int row = idx >> 2, ch = idx & 3;
            uint32_t d = st + swz(row, ch);
            size_t g = (size_t)(m0 + row) * K_TOT + k0 + ch * 8;
            cp16(d + AH_OFF, g_xh + g);
            cp16(d + AL_OFF, g_xl + g);
        }
#pragma unroll
        for (int i = 0; i < 3; i++) {              // B hi+lo: 768 idx
            int idx = tid + i * 256;
            int hl = (idx >= 384);
            int j = idx - hl * 384;
            int row = j >> 2, ch = j & 3;
            uint32_t d = st + (hl ? BL_OFF : BH_OFF) + swz(row, ch);
            const __nv_bfloat16* src = (hl ? g_wl : g_wh);
            cp16(d, src + (size_t)(n0 + row) * K_TOT + k0 + ch * 8);
        }
    };

    // ---- prologue: fill 3 stages ----
#pragma unroll
    for (int s = 0; s < 3; s++) { load_stage(s, s * BK); CP_COMMIT(); }

    // ---- mainloop ----
    for (int t = 0; t < KITERS; t++) {
        CP_WAIT2();
        __syncthreads();             // stage t ready; all warps done with t-1

        if (t + 3 < KITERS) load_stage((t + 3) & 3, (t + 3) * BK);
        CP_COMMIT();

        const uint32_t st = sb + (t & 3) * STAGE_BYTES;
#pragma unroll
        for (int kk = 0; kk < 2; kk++) {
            const uint32_t kx = kk ? 32u : 0u;
            uint32_t a[2][2][4];
#pragma unroll
            for (int mt = 0; mt < 2; mt++) {
                ldm_x4(a[mt][0], st + (aOff[mt][0] ^ kx));
                ldm_x4(a[mt][1], st + (aOff[mt][1] ^ kx));
            }
            uint32_t b[6][2][2];
#pragma unroll
            for (int nt = 0; nt < 6; nt++) {
                ldm_x2(b[nt][0], st + (bOff[nt][0] ^ kx));
                ldm_x2(b[nt][1], st + (bOff[nt][1] ^ kx));
            }
#pragma unroll
            for (int mt = 0; mt < 2; mt++)
#pragma unroll
                for (int nt = 0; nt < 6; nt++) {
                    mma_bf16(acc[mt][nt], a[mt][0], b[nt][0]);  // xh*Wh
                    mma_bf16(acc[mt][nt], a[mt][0], b[nt][1]);  // xh*Wl
                    mma_bf16(acc[mt][nt], a[mt][1], b[nt][0]);  // xl*Wh
                }
        }
    }

    // ---- epilogue: add bias, float2 stores ----
    const int r0 = lane >> 2, c0 = (lane & 3) * 2;
#pragma unroll
    for (int mt = 0; mt < 2; mt++)
#pragma unroll
        for (int nt = 0; nt < 6; nt++) {
            const int col = n0 + wn * 48 + nt * 8 + c0;
            const float bx = bias[col], by = bias[col + 1];
#pragma unroll
            for (int h = 0; h < 2; h++) {
                const int row = m0 + wm * 32 + mt * 16 + r0 + h * 8;
                float2 v;
                v.x = acc[mt][nt][h * 2 + 0] + bx;
                v.y = acc[mt][nt][h * 2 + 1] + by;
                *(float2*)(out + (size_t)row * N_TOT + col) = v;
            }
        }
}

// ---------------------------------------------------------------------------
extern "C" void kernel_launch(void* const* d_in, const int* in_sizes, int n_in,
                              void* d_out, int out_size) {
    const float* x  = (const float*)d_in[0];
    const float* W  = (const float*)d_in[1];
    const float* b  = (const float*)d_in[2];
    const float* lA = (const float*)d_in[3];
    const float* lB = (const float*)d_in[4];
    float* out = (float*)d_out;
    (void)in_sizes; (void)n_in; (void)out_size;

    {   // split x
        size_t total = (size_t)M_TOT * K_TOT / 8;
        convert_x_kernel<<<(unsigned)((total + 255) / 256), 256>>>(x);
    }
    {   // fuse LoRA + split + transpose W
        dim3 grid(N_TOT / 32, K_TOT / 32);
        fuse_w_kernel<<<grid, 256>>>(W, lA, lB);
    }
    {   // bf16 tensor-core GEMM
        cudaFuncSetAttribute(gemm_kernel,
                             cudaFuncAttributeMaxDynamicSharedMemorySize,
                             SMEM_TOTAL);
        dim3 grid(N_TOT / BN, M_TOT / BM);   // (50, 64)
        gemm_kernel<<<grid, 256, SMEM_TOTAL>>>(b, out);
    }
}

// round 4
// speedup vs baseline: 4.0102x; 1.5272x over previous
#include <cuda_runtime.h>
#include <cuda_fp16.h>
#include <cstdint>

// LoRAConv1D: out = x @ W + b + 4.0 * (x @ A) @ B
//   x:[8192,1600]f32  W:[1600,4800]f32  b:[4800]  A:[1600,8]  B:[8,4800]
//
// sm_103 (non-'a' target) tensor path: mma.sync.m16n8k16 fp16.
//  1) W' = W + 4*A@B rounded to fp16, transposed [N,K] (single array)
//  2) x split to fp16 hi + fp16 residual  (x = xh + xl exactly to ~2^-22)
//  3) acc = xh*W + xl*W = x * fp16(W')  -> only error is x*(W'-fp16(W')),
//     rel ~2^-11/sqrt(3) ~ 3e-4 < 1e-3.
//  BM=128 BN=96 BK=32, 4-stage cp.async, 2 CTAs/SM, swizzled ldmatrix.

#define M_TOT 8192
#define N_TOT 4800
#define K_TOT 1600
#define RANK  8

#define BM 128
#define BN 96
#define BK 32
#define KITERS (K_TOT / BK)        // 50
#define STAGES 4

// stage layout (bytes): Ah[128*64] Al[128*64] B[96*64]
#define AH_OFF 0
#define AL_OFF 8192
#define B_OFF  16384
#define STAGE_BYTES 22528
#define SMEM_TOTAL (STAGES * STAGE_BYTES)   // 90112

// ---------------- device scratch (static, alloc-free) ----------------------
__device__ __half g_xh[(size_t)M_TOT * K_TOT];
__device__ __half g_xl[(size_t)M_TOT * K_TOT];
__device__ __half g_w [(size_t)N_TOT * K_TOT];   // [N,K] fused fp16 weight

// ---------------- helpers ---------------------------------------------------
__device__ __forceinline__ uint32_t smem_u32(const void* p) {
    uint32_t a;
    asm("{ .reg .u64 t; cvta.to.shared.u64 t, %1; cvt.u32.u64 %0, t; }"
        : "=r"(a) : "l"(p));
    return a;
}
// swizzled byte offset in a tile (row pitch 64B, 16B chunks), conflict-free
// for both ldmatrix phases and the cp.async writes.
__device__ __forceinline__ uint32_t swz(int row, int ch) {
    return (uint32_t)(row * 64 + 16 * (ch ^ (row & 3) ^ ((row >> 2) & 1)));
}
__device__ __forceinline__ void cp16(uint32_t dst, const void* src) {
    asm volatile("cp.async.cg.shared.global [%0], [%1], 16;"
                 :: "r"(dst), "l"(src));
}
#define CP_COMMIT() asm volatile("cp.async.commit_group;")
#define CP_WAIT2()  asm volatile("cp.async.wait_group 2;")

__device__ __forceinline__ void ldm_x4(uint32_t* r, uint32_t addr) {
    asm volatile("ldmatrix.sync.aligned.m8n8.x4.shared.b16 {%0,%1,%2,%3}, [%4];"
                 : "=r"(r[0]), "=r"(r[1]), "=r"(r[2]), "=r"(r[3]) : "r"(addr));
}
__device__ __forceinline__ void mma_f16(float* d, const uint32_t* a,
                                        const uint32_t* b) {
    asm volatile(
        "mma.sync.aligned.m16n8k16.row.col.f32.f16.f16.f32 "
        "{%0,%1,%2,%3}, {%4,%5,%6,%7}, {%8,%9}, {%0,%1,%2,%3};"
        : "+f"(d[0]), "+f"(d[1]), "+f"(d[2]), "+f"(d[3])
        : "r"(a[0]), "r"(a[1]), "r"(a[2]), "r"(a[3]), "r"(b[0]), "r"(b[1]));
}

// ---------------- kernel 1: split x into fp16 hi/lo -------------------------
__global__ void convert_x_kernel(const float* __restrict__ x) {
    size_t base = ((size_t)blockIdx.x * blockDim.x + threadIdx.x) * 8;
    if (base >= (size_t)M_TOT * K_TOT) return;
    float v[8];
    *(float4*)(v)     = *(const float4*)(x + base);
    *(float4*)(v + 4) = *(const float4*)(x + base + 4);
    uint4 ph, pl;
    __half* hp = (__half*)&ph;
    __half* lp = (__half*)&pl;
#pragma unroll
    for (int j = 0; j < 8; j++) {
        __half h = __float2half_rn(v[j]);
        hp[j] = h;
        lp[j] = __float2half_rn(v[j] - __half2float(h));
    }
    *(uint4*)((char*)g_xh + base * 2) = ph;
    *(uint4*)((char*)g_xl + base * 2) = pl;
}

// ---------------- kernel 2: W' = W + 4*A@B -> fp16, transposed [N,K] --------
__global__ void fuse_w_kernel(const float* __restrict__ W,
                              const float* __restrict__ A,
                              const float* __restrict__ Bl) {
    __shared__ __half sh[32][33];
    const int n0 = blockIdx.x * 32, k0 = blockIdx.y * 32;
    const int tx = threadIdx.x & 31, ty = threadIdx.x >> 5;   // 32 x 8
#pragma unroll
    for (int rr = 0; rr < 4; rr++) {
        int k = k0 + ty + rr * 8, n = n0 + tx;
        float acc = W[(size_t)k * N_TOT + n];
#pragma unroll
        for (int r = 0; r < RANK; r++)
            acc += 4.0f * A[k * RANK + r] * Bl[r * N_TOT + n];
        sh[ty + rr * 8][tx] = __float2half_rn(acc);
    }
    __syncthreads();
#pragma unroll
    for (int rr = 0; rr < 4; rr++) {
        int n = n0 + ty + rr * 8, k = k0 + tx;
        g_w[(size_t)n * K_TOT + k] = sh[tx][ty + rr * 8];
    }
}

// ---------------- kernel 3: fp16 mma.sync GEMM ------------------------------
__global__ __launch_bounds__(256, 2)
void gemm_kernel(const float* __restrict__ bias, float* __restrict__ out) {
    extern __shared__ char smem[];
    const uint32_t sb = smem_u32(smem);
    const int tid = threadIdx.x, lane = tid & 31, wid = tid >> 5;
    const int wm = wid & 3;          // 0..3 -> 32-row slab
    const int wn = wid >> 2;         // 0..1 -> 48-col slab
    const int m0 = blockIdx.y * BM;
    const int n0 = blockIdx.x * BN;

    // ---- ldmatrix address precompute (kk=0; kk=1 is ^32 on the offset) ----
    uint32_t aOff[2][2];             // [mt][hi/lo]
#pragma unroll
    for (int mt = 0; mt < 2; mt++) {
        int row = wm * 32 + mt * 16 + (lane & 15);
        uint32_t o = swz(row, lane >> 4);
        aOff[mt][0] = AH_OFF + o;
        aOff[mt][1] = AL_OFF + o;
    }
    // B: 3 x4-loads per kk; pair p covers nt = 2p (regs 0,1) and 2p+1 (2,3).
    uint32_t bOff[3];
#pragma unroll
    for (int p = 0; p < 3; p++) {
        int row = wn * 48 + (2 * p + ((lane >> 4) & 1)) * 8 + (lane & 7);
        bOff[p] = B_OFF + swz(row, (lane >> 3) & 1);
    }

    float acc[2][6][4];
#pragma unroll
    for (int i = 0; i < 2; i++)
#pragma unroll
        for (int j = 0; j < 6; j++)
#pragma unroll
            for (int k = 0; k < 4; k++) acc[i][j][k] = 0.0f;

    // ---- stage loader: Ah/Al 512 chunks + B 384 chunks of 16B --------------
    auto load_stage = [&](int s, int k0) {
        const uint32_t st = sb + s * STAGE_BYTES;
#pragma unroll
        for (int i = 0; i < 2; i++) {
            int idx = tid + i * 256;
            int row = idx >> 2, ch = idx & 3;
            uint32_t d = st + swz(row, ch);
            size_t g = (size_t)(m0 + row) * K_TOT + k0 + ch * 8;
            cp16(d + AH_OFF, g_xh + g);
            cp16(d + AL_OFF, g_xl + g);
        }
        {
            int row = tid >> 2, ch = tid & 3;
            cp16(st + B_OFF + swz(row, ch),
                 g_w + (size_t)(n0 + row) * K_TOT + k0 + ch * 8);
            if (tid < 128) {
                int idx = tid + 256;
                row = idx >> 2; ch = idx & 3;
                cp16(st + B_OFF + swz(row, ch),
                     g_w + (size_t)(n0 + row) * K_TOT + k0 + ch * 8);
            }
        }
    };

    // ---- prologue: fill 3 stages ----
#pragma unroll
    for (int s = 0; s < 3; s++) { load_stage(s, s * BK); CP_COMMIT(); }

    // ---- mainloop ----
    for (int t = 0; t < KITERS; t++) {
        CP_WAIT2();
        __syncthreads();             // stage t ready; all warps done with t-1

        if (t + 3 < KITERS) load_stage((t + 3) & 3, (t + 3) * BK);
        CP_COMMIT();

        const uint32_t st = sb + (t & 3) * STAGE_BYTES;
#pragma unroll
        for (int kk = 0; kk < 2; kk++) {
            const uint32_t kx = kk ? 32u : 0u;
            uint32_t a[2][2][4];
#pragma unroll
            for (int mt = 0; mt < 2; mt++) {
                ldm_x4(a[mt][0], st + (aOff[mt][0] ^ kx));
                ldm_x4(a[mt][1], st + (aOff[mt][1] ^ kx));
            }
            uint32_t b[3][4];
#pragma unroll
            for (int p = 0; p < 3; p++)
                ldm_x4(b[p], st + (bOff[p] ^ kx));
#pragma unroll
            for (int mt = 0; mt < 2; mt++)
#pragma unroll
                for (int p = 0; p < 3; p++) {
                    mma_f16(acc[mt][2 * p],     a[mt][0], &b[p][0]);  // xh
                    mma_f16(acc[mt][2 * p],     a[mt][1], &b[p][0]);  // xl
                    mma_f16(acc[mt][2 * p + 1], a[mt][0], &b[p][2]);
                    mma_f16(acc[mt][2 * p + 1], a[mt][1], &b[p][2]);
                }
        }
    }

    // ---- epilogue: add bias, float2 stores ----
    const int r0 = lane >> 2, c0 = (lane & 3) * 2;
#pragma unroll
    for (int mt = 0; mt < 2; mt++)
#pragma unroll
        for (int nt = 0; nt < 6; nt++) {
            const int col = n0 + wn * 48 + nt * 8 + c0;
            const float bx = bias[col], by = bias[col + 1];
#pragma unroll
            for (int h = 0; h < 2; h++) {
                const int row = m0 + wm * 32 + mt * 16 + r0 + h * 8;
                float2 v;
                v.x = acc[mt][nt][h * 2 + 0] + bx;
                v.y = acc[mt][nt][h * 2 + 1] + by;
                *(float2*)(out + (size_t)row * N_TOT + col) = v;
            }
        }
}

// ---------------------------------------------------------------------------
extern "C" void kernel_launch(void* const* d_in, const int* in_sizes, int n_in,
                              void* d_out, int out_size) {
    const float* x  = (const float*)d_in[0];
    const float* W  = (const float*)d_in[1];
    const float* b  = (const float*)d_in[2];
    const float* lA = (const float*)d_in[3];
    const float* lB = (const float*)d_in[4];
    float* out = (float*)d_out;
    (void)in_sizes; (void)n_in; (void)out_size;

    {   // split x
        size_t total = (size_t)M_TOT * K_TOT / 8;
        convert_x_kernel<<<(unsigned)((total + 255) / 256), 256>>>(x);
    }
    {   // fuse LoRA + round + transpose W
        dim3 grid(N_TOT / 32, K_TOT / 32);
        fuse_w_kernel<<<grid, 256>>>(W, lA, lB);
    }
    {   // fp16 tensor-core GEMM
        cudaFuncSetAttribute(gemm_kernel,
                             cudaFuncAttributeMaxDynamicSharedMemorySize,
                             SMEM_TOTAL);
        dim3 grid(N_TOT / BN, M_TOT / BM);   // (50, 64)
        gemm_kernel<<<grid, 256, SMEM_TOTAL>>>(b, out);
    }
}